// round 14
// baseline (speedup 1.0000x reference)
#include <cuda_runtime.h>
#include <cuda_bf16.h>
#include <math.h>
#include <float.h>

// Problem constants
#define SEQ 4096
#define DM  512
#define FF  2048
#define NH  8
#define DH  64

// ---------------- scratch (allocation-free: __device__ globals) ----------------
__device__ float g_q[SEQ * DM];
__device__ float g_k[SEQ * DM];
__device__ float g_v[SEQ * DM];
__device__ float g_attn[SEQ * DM];
__device__ float g_tmp[SEQ * DM];
__device__ float g_y[SEQ * DM];
__device__ float g_h[SEQ * FF];

// ---------------- packed f32x2 FMA (Blackwell FFMA2, PTX-only) ----------------
union f2u { float2 f; unsigned long long u; };

__device__ __forceinline__ float2 ffma2(float2 a, float2 b, float2 c)
{
    f2u A, B, C, D;
    A.f = a; B.f = b; C.f = c;
    asm("fma.rn.f32x2 %0, %1, %2, %3;" : "=l"(D.u) : "l"(A.u), "l"(B.u), "l"(C.u));
    return D.f;
}

// ---------------- mma.sync helpers (portable tensor path, sm_80+) -------------
__device__ __forceinline__ unsigned smem_u32(const void* p)
{
    unsigned a;
    asm("{ .reg .u64 t; cvta.to.shared.u64 t, %1; cvt.u32.u64 %0, t; }"
        : "=r"(a) : "l"(p));
    return a;
}

__device__ __forceinline__ void ldsm4(unsigned* r, unsigned addr)
{
    asm volatile("ldmatrix.sync.aligned.m8n8.x4.shared.b16 {%0,%1,%2,%3}, [%4];"
                 : "=r"(r[0]), "=r"(r[1]), "=r"(r[2]), "=r"(r[3]) : "r"(addr));
}

// D = A(16x16 bf16,row) * B(16x8 bf16,col) + D, fp32 accum
__device__ __forceinline__ void mma16816(float* c, const unsigned* a,
                                         const unsigned* b)
{
    asm volatile("mma.sync.aligned.m16n8k16.row.col.f32.bf16.bf16.f32 "
                 "{%0,%1,%2,%3}, {%4,%5,%6,%7}, {%8,%9}, {%0,%1,%2,%3};"
                 : "+f"(c[0]), "+f"(c[1]), "+f"(c[2]), "+f"(c[3])
                 : "r"(a[0]), "r"(a[1]), "r"(a[2]), "r"(a[3]),
                   "r"(b[0]), "r"(b[1]));
}

// fp32 -> bf16 hi + bf16 lo(remainder)
__device__ __forceinline__ void bf16split(float f, unsigned short& h,
                                          unsigned short& l)
{
    __nv_bfloat16 hb = __float2bfloat16(f);
    float rem = f - __bfloat162float(hb);
    __nv_bfloat16 lb = __float2bfloat16(rem);
    h = __bfloat16_as_ushort(hb);
    l = __bfloat16_as_ushort(lb);
}

// ---------------- tensor-core GEMM: C[M,N] = A[M,K]@B[K,N] + bias, opt ReLU --
// CTA: 128x64 tile, BK=32 chunks. 256 threads = 8 warps (4 x 2), warp 32x32.
// bf16 hi/lo 3-product split, fp32 accumulate in registers.
// smem: A [128][40] bf16 (pad 40: 80B row stride, 16B-aligned, ldmatrix
// conflict-free), B transposed [n=64][k=40].
#define ASTR 40

template <bool RELU>
__device__ __forceinline__
void gemm_mma_body(const float* __restrict__ A, const float* __restrict__ B,
                   const float* __restrict__ bias, float* __restrict__ C,
                   int N, int K, int m0, int n0)
{
    __shared__ __align__(16) unsigned short sAh[128 * ASTR];
    __shared__ __align__(16) unsigned short sAl[128 * ASTR];
    __shared__ __align__(16) unsigned short sBh[64 * ASTR];
    __shared__ __align__(16) unsigned short sBl[64 * ASTR];

    const int tid  = threadIdx.x;
    const int wid  = tid >> 5;
    const int lane = tid & 31;
    const int wm   = wid >> 1;    // 0..3 -> rows wm*32..+31
    const int wn   = wid & 1;     // 0..1 -> cols wn*32..+31

    float c[2][4][4];
#pragma unroll
    for (int mt = 0; mt < 2; ++mt)
#pragma unroll
        for (int nt = 0; nt < 4; ++nt)
#pragma unroll
            for (int i = 0; i < 4; ++i) c[mt][nt][i] = 0.f;

    const unsigned baseAh = smem_u32(sAh), baseAl = smem_u32(sAl);
    const unsigned baseBh = smem_u32(sBh), baseBl = smem_u32(sBl);

    // B-load decomposition: thread -> (n, k-group)
    const int nn = tid & 63;          // 0..63
    const int kg = tid >> 6;          // 0..3 -> k = kg*8 + j

    const int nchunks = K >> 5;       // BK = 32
    for (int ch = 0; ch < nchunks; ++ch) {
        const int k0 = ch << 5;

        // ---- A tile 128x32 fp32 -> bf16 hi/lo ----
#pragma unroll
        for (int it = 0; it < 2; ++it) {
            int idx = tid + it * 256;          // 0..511
            int row = idx >> 2, seg = idx & 3; // 8 floats per thread
            const float* ap = A + (size_t)(m0 + row) * K + k0 + seg * 8;
            float4 a0 = *(const float4*)ap;
            float4 a1 = *(const float4*)(ap + 4);
            float f[8] = {a0.x, a0.y, a0.z, a0.w, a1.x, a1.y, a1.z, a1.w};
            union { unsigned short u[8]; uint4 v; } H, L;
#pragma unroll
            for (int i = 0; i < 8; ++i) bf16split(f[i], H.u[i], L.u[i]);
            int so = row * ASTR + seg * 8;     // 16B aligned (80B stride)
            *(uint4*)(sAh + so) = H.v;
            *(uint4*)(sAl + so) = L.v;
        }

        // ---- B tile 32(k)x64(n) fp32 -> transposed [n][k] bf16 hi/lo ----
#pragma unroll
        for (int jj = 0; jj < 4; ++jj) {
            int k = kg * 8 + jj * 2;
            float f0 = B[(size_t)(k0 + k + 0) * N + n0 + nn];
            float f1 = B[(size_t)(k0 + k + 1) * N + n0 + nn];
            unsigned short h0, l0, h1, l1;
            bf16split(f0, h0, l0);
            bf16split(f1, h1, l1);
            int so = nn * ASTR + k;            // 4B aligned
            *(unsigned*)(sBh + so) = (unsigned)h0 | ((unsigned)h1 << 16);
            *(unsigned*)(sBl + so) = (unsigned)l0 | ((unsigned)l1 << 16);
        }
        __syncthreads();

        // ---- compute: 2 k16-steps ----
#pragma unroll
        for (int ks = 0; ks < 2; ++ks) {
            // A fragment addresses: quads (lane>>3): row +8 on bit0, k +8 on bit1
            unsigned ah[2][4], al[2][4];
#pragma unroll
            for (int mt = 0; mt < 2; ++mt) {
                int row = wm * 32 + mt * 16 + (lane & 7) + ((lane >> 3) & 1) * 8;
                int kc  = ks * 16 + (lane >> 4) * 8;
                unsigned off = (unsigned)(row * ASTR + kc) * 2;
                ldsm4(ah[mt], baseAh + off);
                ldsm4(al[mt], baseAl + off);
            }
            // B fragments: each x4 covers 2 n-tiles (quads: k +8 on bit0 of
            // lane>>3, n +8 on bit1)
            unsigned bh[4][2], bl[4][2];
#pragma unroll
            for (int ntp = 0; ntp < 2; ++ntp) {
                int nrow = wn * 32 + ntp * 16 + (lane & 7) + ((lane >> 4) & 1) * 8;
                int kc   = ks * 16 + ((lane >> 3) & 1) * 8;
                unsigned off = (unsigned)(nrow * ASTR + kc) * 2;
                unsigned t[4];
                ldsm4(t, baseBh + off);
                bh[ntp * 2 + 0][0] = t[0]; bh[ntp * 2 + 0][1] = t[1];
                bh[ntp * 2 + 1][0] = t[2]; bh[ntp * 2 + 1][1] = t[3];
                ldsm4(t, baseBl + off);
                bl[ntp * 2 + 0][0] = t[0]; bl[ntp * 2 + 0][1] = t[1];
                bl[ntp * 2 + 1][0] = t[2]; bl[ntp * 2 + 1][1] = t[3];
            }
#pragma unroll
            for (int mt = 0; mt < 2; ++mt)
#pragma unroll
                for (int nt = 0; nt < 4; ++nt) {
                    mma16816(c[mt][nt], ah[mt], bh[nt]);
                    mma16816(c[mt][nt], ah[mt], bl[nt]);
                    mma16816(c[mt][nt], al[mt], bh[nt]);
                }
        }
        __syncthreads();
    }

    // ---- epilogue: c0,c1 -> (row, col..col+1); c2,c3 -> (row+8, ..) ----
    const int gid = lane >> 2;        // groupID
    const int tig = lane & 3;
#pragma unroll
    for (int mt = 0; mt < 2; ++mt) {
        int row = m0 + wm * 32 + mt * 16 + gid;
#pragma unroll
        for (int nt = 0; nt < 4; ++nt) {
            int col = n0 + wn * 32 + nt * 8 + tig * 2;
            float2 bb = *(const float2*)(bias + col);
            float2 o0, o1;
            o0.x = c[mt][nt][0] + bb.x;
            o0.y = c[mt][nt][1] + bb.y;
            o1.x = c[mt][nt][2] + bb.x;
            o1.y = c[mt][nt][3] + bb.y;
            if (RELU) {
                o0.x = fmaxf(o0.x, 0.f); o0.y = fmaxf(o0.y, 0.f);
                o1.x = fmaxf(o1.x, 0.f); o1.y = fmaxf(o1.y, 0.f);
            }
            *(float2*)(C + (size_t)row * N + col)       = o0;
            *(float2*)(C + (size_t)(row + 8) * N + col) = o1;
        }
    }
}

template <bool RELU>
__global__ __launch_bounds__(256)
void gemm_mma(const float* __restrict__ A, const float* __restrict__ B,
              const float* __restrict__ bias, float* __restrict__ C,
              int N, int K)
{
    gemm_mma_body<RELU>(A, B, bias, C, N, K, blockIdx.y * 128, blockIdx.x * 64);
}

// Fused Q/K/V projection (blockIdx.z selects weights/bias/output)
__global__ __launch_bounds__(256)
void qkv_mma(const float* __restrict__ X,
             const float* __restrict__ Wq, const float* __restrict__ Bq, float* __restrict__ Oq,
             const float* __restrict__ Wk, const float* __restrict__ Bk, float* __restrict__ Ok,
             const float* __restrict__ Wv, const float* __restrict__ Bv, float* __restrict__ Ov)
{
    const float* W; const float* Bb; float* O;
    if (blockIdx.z == 0)      { W = Wq; Bb = Bq; O = Oq; }
    else if (blockIdx.z == 1) { W = Wk; Bb = Bk; O = Ok; }
    else                      { W = Wv; Bb = Bv; O = Ov; }
    gemm_mma_body<false>(X, W, Bb, O, DM, DM, blockIdx.y * 128, blockIdx.x * 64);
}

// ---------------- Flash attention, fp32, online softmax (R8-passing) ---------
#define SSTR 68
__global__ __launch_bounds__(256)
void attn_kernel(const float* __restrict__ Q, const float* __restrict__ Kg,
                 const float* __restrict__ Vg, const int* __restrict__ mask,
                 float* __restrict__ O)
{
    const int head = blockIdx.y;
    const int q0 = blockIdx.x * 64;
    const int tid = threadIdx.x;
    const int tr = tid >> 4;
    const int tc = tid & 15;

    extern __shared__ float sm[];
    float* sQ = sm;
    float* sK = sm + 64 * SSTR;
    float* sV = sm + 2 * 64 * SSTR;
    float* sP = sK;   // alias: K tile is dead after the score phase

#pragma unroll
    for (int l = 0; l < 4; ++l) {
        int idx = tid + l * 256;
        int r = idx >> 4, c4 = idx & 15;
        *(float4*)(sQ + r * SSTR + c4 * 4) =
            *(const float4*)(Q + (size_t)(q0 + r) * DM + head * DH + c4 * 4);
    }

    float mrow[4], lrow[4];
    float2 acc2[4][2];
#pragma unroll
    for (int r = 0; r < 4; ++r) {
        mrow[r] = -3.0e38f;
        lrow[r] = 0.f;
        acc2[r][0] = make_float2(0.f, 0.f);
        acc2[r][1] = make_float2(0.f, 0.f);
    }

    for (int k0 = 0; k0 < SEQ; k0 += 64) {
        int mreg[4][4];
#pragma unroll
        for (int r = 0; r < 4; ++r) {
            const int* mp = mask + (size_t)(q0 + tr * 4 + r) * SEQ + k0;
#pragma unroll
            for (int c = 0; c < 4; ++c)
                mreg[r][c] = __ldg(mp + tc + 16 * c);
        }

#pragma unroll
        for (int l = 0; l < 4; ++l) {
            int idx = tid + l * 256;
            int r = idx >> 4, c4 = idx & 15;
            *(float4*)(sK + r * SSTR + c4 * 4) =
                *(const float4*)(Kg + (size_t)(k0 + r) * DM + head * DH + c4 * 4);
            *(float4*)(sV + r * SSTR + c4 * 4) =
                *(const float4*)(Vg + (size_t)(k0 + r) * DM + head * DH + c4 * 4);
        }
        __syncthreads();

        float2 s2[4][4];
#pragma unroll
        for (int r = 0; r < 4; ++r)
#pragma unroll
            for (int c = 0; c < 4; ++c) s2[r][c] = make_float2(0.f, 0.f);

#pragma unroll
        for (int d = 0; d < DH; d += 4) {
            float4 qv[4], kv[4];
#pragma unroll
            for (int r = 0; r < 4; ++r)
                qv[r] = *(const float4*)(sQ + (tr * 4 + r) * SSTR + d);
#pragma unroll
            for (int c = 0; c < 4; ++c)
                kv[c] = *(const float4*)(sK + (tc + 16 * c) * SSTR + d);
#pragma unroll
            for (int r = 0; r < 4; ++r) {
                float2 q01 = make_float2(qv[r].x, qv[r].y);
                float2 q23 = make_float2(qv[r].z, qv[r].w);
#pragma unroll
                for (int c = 0; c < 4; ++c) {
                    s2[r][c] = ffma2(q01, make_float2(kv[c].x, kv[c].y), s2[r][c]);
                    s2[r][c] = ffma2(q23, make_float2(kv[c].z, kv[c].w), s2[r][c]);
                }
            }
        }

        float s[4][4];
#pragma unroll
        for (int r = 0; r < 4; ++r)
#pragma unroll
            for (int c = 0; c < 4; ++c) {
                s[r][c] = s2[r][c].x + s2[r][c].y;
                if (mreg[r][c] == 0) s[r][c] = -1.0e9f;
            }

        __syncthreads();

#pragma unroll
        for (int r = 0; r < 4; ++r) {
            float tm = fmaxf(fmaxf(s[r][0], s[r][1]), fmaxf(s[r][2], s[r][3]));
#pragma unroll
            for (int off = 8; off >= 1; off >>= 1)
                tm = fmaxf(tm, __shfl_xor_sync(0xffffffffu, tm, off));
            float nm = fmaxf(mrow[r], tm);
            float sc = __expf(mrow[r] - nm);
            mrow[r] = nm;
            float rs = 0.f;
#pragma unroll
            for (int c = 0; c < 4; ++c) {
                float p = __expf(s[r][c] - nm);
                rs += p;
                sP[(tr * 4 + r) * SSTR + tc + 16 * c] = p;
            }
#pragma unroll
            for (int off = 8; off >= 1; off >>= 1)
                rs += __shfl_xor_sync(0xffffffffu, rs, off);
            lrow[r] = lrow[r] * sc + rs;
            acc2[r][0].x *= sc; acc2[r][0].y *= sc;
            acc2[r][1].x *= sc; acc2[r][1].y *= sc;
        }
        __syncthreads();

#pragma unroll 8
        for (int j = 0; j < 64; ++j) {
            float4 vv = *(const float4*)(sV + j * SSTR + tc * 4);
            float2 v0 = make_float2(vv.x, vv.y);
            float2 v1 = make_float2(vv.z, vv.w);
#pragma unroll
            for (int r = 0; r < 4; ++r) {
                float p = sP[(tr * 4 + r) * SSTR + j];
                float2 pp = make_float2(p, p);
                acc2[r][0] = ffma2(pp, v0, acc2[r][0]);
                acc2[r][1] = ffma2(pp, v1, acc2[r][1]);
            }
        }
        __syncthreads();
    }

#pragma unroll
    for (int r = 0; r < 4; ++r) {
        float inv = 1.f / lrow[r];
        float4 o = make_float4(acc2[r][0].x * inv, acc2[r][0].y * inv,
                               acc2[r][1].x * inv, acc2[r][1].y * inv);
        *(float4*)(O + (size_t)(q0 + tr * 4 + r) * DM + head * DH + tc * 4) = o;
    }
}

// ---------------- residual + LayerNorm: out = LN(X + R) * g + b --------------
__global__ __launch_bounds__(256)
void ln_res_kernel(const float* __restrict__ X, const float* __restrict__ R,
                   const float* __restrict__ g, const float* __restrict__ b,
                   float* __restrict__ out)
{
    __shared__ float red[8];
    __shared__ float stat[2];
    const int row = blockIdx.x;
    const int tid = threadIdx.x;
    const int col = tid * 2;

    float2 xv = *(const float2*)(X + (size_t)row * DM + col);
    float2 rv = *(const float2*)(R + (size_t)row * DM + col);
    float a0 = xv.x + rv.x;
    float a1 = xv.y + rv.y;

    float s = a0 + a1;
#pragma unroll
    for (int off = 16; off >= 1; off >>= 1)
        s += __shfl_xor_sync(0xffffffffu, s, off);
    if ((tid & 31) == 0) red[tid >> 5] = s;
    __syncthreads();
    if (tid == 0) {
        float t = 0.f;
#pragma unroll
        for (int i = 0; i < 8; ++i) t += red[i];
        stat[0] = t * (1.f / (float)DM);
    }
    __syncthreads();
    const float mean = stat[0];

    float d0 = a0 - mean, d1 = a1 - mean;
    float sq = d0 * d0 + d1 * d1;
#pragma unroll
    for (int off = 16; off >= 1; off >>= 1)
        sq += __shfl_xor_sync(0xffffffffu, sq, off);
    if ((tid & 31) == 0) red[tid >> 5] = sq;
    __syncthreads();
    if (tid == 0) {
        float t = 0.f;
#pragma unroll
        for (int i = 0; i < 8; ++i) t += red[i];
        stat[1] = t * (1.f / (float)DM);
    }
    __syncthreads();
    const float rstd = rsqrtf(stat[1] + 1e-5f);

    float2 gv = *(const float2*)(g + col);
    float2 bv = *(const float2*)(b + col);
    float2 o;
    o.x = d0 * rstd * gv.x + bv.x;
    o.y = d1 * rstd * gv.y + bv.y;
    *(float2*)(out + (size_t)row * DM + col) = o;
}

// ---------------- launch ------------------------------------------------------
extern "C" void kernel_launch(void* const* d_in, const int* in_sizes, int n_in,
                              void* d_out, int out_size)
{
    (void)in_sizes; (void)n_in; (void)out_size;

    const float* x   = (const float*)d_in[0];
    const int*   msk = (const int*)  d_in[1];
    const float* wq  = (const float*)d_in[2];
    const float* bq  = (const float*)d_in[3];
    const float* wk  = (const float*)d_in[4];
    const float* bk  = (const float*)d_in[5];
    const float* wv  = (const float*)d_in[6];
    const float* bv  = (const float*)d_in[7];
    const float* wo  = (const float*)d_in[8];
    const float* bo  = (const float*)d_in[9];
    const float* w1  = (const float*)d_in[10];
    const float* b1  = (const float*)d_in[11];
    const float* w2  = (const float*)d_in[12];
    const float* b2  = (const float*)d_in[13];
    const float* g1  = (const float*)d_in[14];
    const float* be1 = (const float*)d_in[15];
    const float* g2  = (const float*)d_in[16];
    const float* be2 = (const float*)d_in[17];
    float* out = (float*)d_out;

    float *q, *k, *v, *attn, *tmp, *y, *h;
    cudaGetSymbolAddress((void**)&q,    g_q);
    cudaGetSymbolAddress((void**)&k,    g_k);
    cudaGetSymbolAddress((void**)&v,    g_v);
    cudaGetSymbolAddress((void**)&attn, g_attn);
    cudaGetSymbolAddress((void**)&tmp,  g_tmp);
    cudaGetSymbolAddress((void**)&y,    g_y);
    cudaGetSymbolAddress((void**)&h,    g_h);

    const dim3 blk(256);

    // Q/K/V projections (mma.sync bf16-split tensor cores, fused launch)
    qkv_mma<<<dim3(DM / 64, SEQ / 128, 3), blk>>>(
        x, wq, bq, q, wk, bk, k, wv, bv, v);

    // attention (fp32 flash)
    const int asmem = 3 * 64 * SSTR * (int)sizeof(float);
    cudaFuncSetAttribute(attn_kernel, cudaFuncAttributeMaxDynamicSharedMemorySize, asmem);
    attn_kernel<<<dim3(SEQ / 64, NH), blk, asmem>>>(q, k, v, msk, attn);

    // output projection + residual + LN1
    gemm_mma<false><<<dim3(DM / 64, SEQ / 128), blk>>>(attn, wo, bo, tmp, DM, DM);
    ln_res_kernel<<<SEQ, blk>>>(x, tmp, g1, be1, y);

    // FFN
    gemm_mma<true ><<<dim3(FF / 64, SEQ / 128), blk>>>(y, w1, b1, h, FF, DM);
    gemm_mma<false><<<dim3(DM / 64, SEQ / 128), blk>>>(h, w2, b2, tmp, DM, FF);
    ln_res_kernel<<<SEQ, blk>>>(y, tmp, g2, be2, out);
}

// round 16
// speedup vs baseline: 1.6133x; 1.6133x over previous
#include <cuda_runtime.h>
#include <cuda_bf16.h>
#include <math.h>
#include <float.h>

// Problem constants
#define SEQ 4096
#define DM  512
#define FF  2048
#define NH  8
#define DH  64

typedef unsigned short u16;

// ---------------- scratch (allocation-free: __device__ globals) ----------------
__device__ float g_q[SEQ * DM];
__device__ float g_k[SEQ * DM];
__device__ float g_v[SEQ * DM];
__device__ float g_tmp[SEQ * DM];
__device__ float g_y[SEQ * DM];

// bf16 hi/lo operand buffers
__device__ u16 g_xh[SEQ * DM],  g_xl[SEQ * DM];    // split(x)
__device__ u16 g_ah[SEQ * DM],  g_al[SEQ * DM];    // attention output
__device__ u16 g_yh[SEQ * DM],  g_yl[SEQ * DM];    // LN1 output
__device__ u16 g_hh[SEQ * FF],  g_hl[SEQ * FF];    // FFN1 ReLU output
// transposed weights [N][K]
__device__ u16 g_wqh[DM * DM], g_wql[DM * DM];
__device__ u16 g_wkh[DM * DM], g_wkl[DM * DM];
__device__ u16 g_wvh[DM * DM], g_wvl[DM * DM];
__device__ u16 g_woh[DM * DM], g_wol[DM * DM];
__device__ u16 g_w1h[FF * DM], g_w1l[FF * DM];     // [FF][DM]
__device__ u16 g_w2h[DM * FF], g_w2l[DM * FF];     // [DM][FF]

// ---------------- packed f32x2 FMA (Blackwell FFMA2, PTX-only) ----------------
union f2u { float2 f; unsigned long long u; };

__device__ __forceinline__ float2 ffma2(float2 a, float2 b, float2 c)
{
    f2u A, B, C, D;
    A.f = a; B.f = b; C.f = c;
    asm("fma.rn.f32x2 %0, %1, %2, %3;" : "=l"(D.u) : "l"(A.u), "l"(B.u), "l"(C.u));
    return D.f;
}

// ---------------- helpers -----------------------------------------------------
__device__ __forceinline__ unsigned smem_u32(const void* p)
{
    unsigned a;
    asm("{ .reg .u64 t; cvta.to.shared.u64 t, %1; cvt.u32.u64 %0, t; }"
        : "=r"(a) : "l"(p));
    return a;
}

__device__ __forceinline__ void ldsm4(unsigned* r, unsigned addr)
{
    asm volatile("ldmatrix.sync.aligned.m8n8.x4.shared.b16 {%0,%1,%2,%3}, [%4];"
                 : "=r"(r[0]), "=r"(r[1]), "=r"(r[2]), "=r"(r[3]) : "r"(addr));
}

__device__ __forceinline__ void mma16816(float* c, const unsigned* a,
                                         const unsigned* b)
{
    asm volatile("mma.sync.aligned.m16n8k16.row.col.f32.bf16.bf16.f32 "
                 "{%0,%1,%2,%3}, {%4,%5,%6,%7}, {%8,%9}, {%0,%1,%2,%3};"
                 : "+f"(c[0]), "+f"(c[1]), "+f"(c[2]), "+f"(c[3])
                 : "r"(a[0]), "r"(a[1]), "r"(a[2]), "r"(a[3]),
                   "r"(b[0]), "r"(b[1]));
}

__device__ __forceinline__ void bf16split(float f, u16& h, u16& l)
{
    __nv_bfloat16 hb = __float2bfloat16(f);
    float rem = f - __bfloat162float(hb);
    __nv_bfloat16 lb = __float2bfloat16(rem);
    h = __bfloat16_as_ushort(hb);
    l = __bfloat16_as_ushort(lb);
}

// ---------------- conversion kernels ------------------------------------------
// elementwise split: fp32 [n] -> bf16 hi/lo (packed pair stores)
__global__ __launch_bounds__(256)
void split_act(const float* __restrict__ X, u16* __restrict__ H,
               u16* __restrict__ L, int n)
{
    int i = (blockIdx.x * 256 + threadIdx.x) * 4;
    if (i >= n) return;
    float4 f = *(const float4*)(X + i);
    u16 h0, l0, h1, l1, h2, l2, h3, l3;
    bf16split(f.x, h0, l0); bf16split(f.y, h1, l1);
    bf16split(f.z, h2, l2); bf16split(f.w, h3, l3);
    uint2 hv, lv;
    hv.x = (unsigned)h0 | ((unsigned)h1 << 16);
    hv.y = (unsigned)h2 | ((unsigned)h3 << 16);
    lv.x = (unsigned)l0 | ((unsigned)l1 << 16);
    lv.y = (unsigned)l2 | ((unsigned)l3 << 16);
    *(uint2*)(H + i) = hv;
    *(uint2*)(L + i) = lv;
}

// W [K][N] fp32 -> T [N][K] bf16 hi/lo (tiled transpose)
__global__ __launch_bounds__(256)
void transpose_split(const float* __restrict__ W, u16* __restrict__ Th,
                     u16* __restrict__ Tl, int K, int N)
{
    __shared__ float tile[32][33];
    const int k0 = blockIdx.y * 32, n0 = blockIdx.x * 32;
    const int tx = threadIdx.x & 31, ty = threadIdx.x >> 5;
#pragma unroll
    for (int i = 0; i < 32; i += 8)
        tile[ty + i][tx] = W[(size_t)(k0 + ty + i) * N + n0 + tx];
    __syncthreads();
#pragma unroll
    for (int i = 0; i < 32; i += 8) {
        float f = tile[tx][ty + i];           // W[k0+tx][n0+ty+i]
        u16 h, l;
        bf16split(f, h, l);
        size_t o = (size_t)(n0 + ty + i) * K + k0 + tx;
        Th[o] = h;
        Tl[o] = l;
    }
}

// ---------------- tensor-core GEMM on pre-split bf16 --------------------------
// C[M,N] = A[M,K] @ B^T  (A row-major [M][K] hi/lo, B pre-transposed [N][K]).
// CTA 128x64, BK=32, 256 threads = 8 warps (4x2), warp 32x32.
// 3-product hi/lo split, fp32 accum. Epilogue: fp32 C and/or bf16 hi/lo C.
#define ASTR 40

template <bool RELU, bool OUT_BF16>
__device__ __forceinline__
void gemm_mma_body(const u16* __restrict__ Ah, const u16* __restrict__ Al,
                   const u16* __restrict__ Bh, const u16* __restrict__ Bl,
                   const float* __restrict__ bias,
                   float* __restrict__ C, u16* __restrict__ Ch,
                   u16* __restrict__ Cl, int N, int K, int m0, int n0)
{
    __shared__ __align__(16) u16 sAh[128 * ASTR];
    __shared__ __align__(16) u16 sAl[128 * ASTR];
    __shared__ __align__(16) u16 sBh[64 * ASTR];
    __shared__ __align__(16) u16 sBl[64 * ASTR];

    const int tid  = threadIdx.x;
    const int wid  = tid >> 5;
    const int lane = tid & 31;
    const int wm   = wid >> 1;
    const int wn   = wid & 1;

    float c[2][4][4];
#pragma unroll
    for (int mt = 0; mt < 2; ++mt)
#pragma unroll
        for (int nt = 0; nt < 4; ++nt)
#pragma unroll
            for (int i = 0; i < 4; ++i) c[mt][nt][i] = 0.f;

    const unsigned baseAh = smem_u32(sAh), baseAl = smem_u32(sAl);
    const unsigned baseBh = smem_u32(sBh), baseBl = smem_u32(sBl);

    const int nchunks = K >> 5;
    for (int ch = 0; ch < nchunks; ++ch) {
        const int k0 = ch << 5;

        // A tile 128x32: 512 uint4 per buffer; 2 per thread
#pragma unroll
        for (int it = 0; it < 2; ++it) {
            int idx = tid + it * 256;
            int row = idx >> 2, seg = idx & 3;
            size_t go = (size_t)(m0 + row) * K + k0 + seg * 8;
            int so = row * ASTR + seg * 8;
            *(uint4*)(sAh + so) = *(const uint4*)(Ah + go);
            *(uint4*)(sAl + so) = *(const uint4*)(Al + go);
        }
        // B tile 64x32: 256 uint4 per buffer; 1 per thread
        {
            int row = tid >> 2, seg = tid & 3;
            size_t go = (size_t)(n0 + row) * K + k0 + seg * 8;
            int so = row * ASTR + seg * 8;
            *(uint4*)(sBh + so) = *(const uint4*)(Bh + go);
            *(uint4*)(sBl + so) = *(const uint4*)(Bl + go);
        }
        __syncthreads();

#pragma unroll
        for (int ks = 0; ks < 2; ++ks) {
            unsigned ah[2][4], al[2][4];
#pragma unroll
            for (int mt = 0; mt < 2; ++mt) {
                int row = wm * 32 + mt * 16 + (lane & 7) + ((lane >> 3) & 1) * 8;
                int kc  = ks * 16 + (lane >> 4) * 8;
                unsigned off = (unsigned)(row * ASTR + kc) * 2;
                ldsm4(ah[mt], baseAh + off);
                ldsm4(al[mt], baseAl + off);
            }
            unsigned bh[4][2], bl[4][2];
#pragma unroll
            for (int ntp = 0; ntp < 2; ++ntp) {
                int nrow = wn * 32 + ntp * 16 + (lane & 7) + ((lane >> 4) & 1) * 8;
                int kc   = ks * 16 + ((lane >> 3) & 1) * 8;
                unsigned off = (unsigned)(nrow * ASTR + kc) * 2;
                unsigned t[4];
                ldsm4(t, baseBh + off);
                bh[ntp * 2 + 0][0] = t[0]; bh[ntp * 2 + 0][1] = t[1];
                bh[ntp * 2 + 1][0] = t[2]; bh[ntp * 2 + 1][1] = t[3];
                ldsm4(t, baseBl + off);
                bl[ntp * 2 + 0][0] = t[0]; bl[ntp * 2 + 0][1] = t[1];
                bl[ntp * 2 + 1][0] = t[2]; bl[ntp * 2 + 1][1] = t[3];
            }
#pragma unroll
            for (int mt = 0; mt < 2; ++mt)
#pragma unroll
                for (int nt = 0; nt < 4; ++nt) {
                    mma16816(c[mt][nt], ah[mt], bh[nt]);
                    mma16816(c[mt][nt], ah[mt], bl[nt]);
                    mma16816(c[mt][nt], al[mt], bh[nt]);
                }
        }
        __syncthreads();
    }

    const int gid = lane >> 2;
    const int tig = lane & 3;
#pragma unroll
    for (int mt = 0; mt < 2; ++mt) {
        int row = m0 + wm * 32 + mt * 16 + gid;
#pragma unroll
        for (int nt = 0; nt < 4; ++nt) {
            int col = n0 + wn * 32 + nt * 8 + tig * 2;
            float2 bb = *(const float2*)(bias + col);
            float o00 = c[mt][nt][0] + bb.x;
            float o01 = c[mt][nt][1] + bb.y;
            float o10 = c[mt][nt][2] + bb.x;
            float o11 = c[mt][nt][3] + bb.y;
            if (RELU) {
                o00 = fmaxf(o00, 0.f); o01 = fmaxf(o01, 0.f);
                o10 = fmaxf(o10, 0.f); o11 = fmaxf(o11, 0.f);
            }
            if (OUT_BF16) {
                u16 h0, l0, h1, l1;
                bf16split(o00, h0, l0); bf16split(o01, h1, l1);
                *(unsigned*)(Ch + (size_t)row * N + col) =
                    (unsigned)h0 | ((unsigned)h1 << 16);
                *(unsigned*)(Cl + (size_t)row * N + col) =
                    (unsigned)l0 | ((unsigned)l1 << 16);
                bf16split(o10, h0, l0); bf16split(o11, h1, l1);
                *(unsigned*)(Ch + (size_t)(row + 8) * N + col) =
                    (unsigned)h0 | ((unsigned)h1 << 16);
                *(unsigned*)(Cl + (size_t)(row + 8) * N + col) =
                    (unsigned)l0 | ((unsigned)l1 << 16);
            } else {
                float2 a = make_float2(o00, o01), b2 = make_float2(o10, o11);
                *(float2*)(C + (size_t)row * N + col)       = a;
                *(float2*)(C + (size_t)(row + 8) * N + col) = b2;
            }
        }
    }
}

template <bool RELU, bool OUT_BF16>
__global__ __launch_bounds__(256)
void gemm_mma(const u16* __restrict__ Ah, const u16* __restrict__ Al,
              const u16* __restrict__ Bh, const u16* __restrict__ Bl,
              const float* __restrict__ bias, float* __restrict__ C,
              u16* __restrict__ Ch, u16* __restrict__ Cl, int N, int K)
{
    gemm_mma_body<RELU, OUT_BF16>(Ah, Al, Bh, Bl, bias, C, Ch, Cl,
                                  N, K, blockIdx.y * 128, blockIdx.x * 64);
}

// Fused Q/K/V projection (blockIdx.z selects weights/bias/output)
__global__ __launch_bounds__(256)
void qkv_mma(const u16* __restrict__ Xh, const u16* __restrict__ Xl,
             const float* __restrict__ Bq, const float* __restrict__ Bk,
             const float* __restrict__ Bv,
             float* __restrict__ Oq, float* __restrict__ Ok,
             float* __restrict__ Ov)
{
    const u16* Wh; const u16* Wl; const float* Bb; float* O;
    if (blockIdx.z == 0)      { Wh = g_wqh; Wl = g_wql; Bb = Bq; O = Oq; }
    else if (blockIdx.z == 1) { Wh = g_wkh; Wl = g_wkl; Bb = Bk; O = Ok; }
    else                      { Wh = g_wvh; Wl = g_wvl; Bb = Bv; O = Ov; }
    gemm_mma_body<false, false>(Xh, Xl, Wh, Wl, Bb, O, 0, 0,
                                DM, DM, blockIdx.y * 128, blockIdx.x * 64);
}

// ---------------- Flash attention, fp32 FFMA2 (R8) + bf16 split epilogue -----
#define SSTR 68
__global__ __launch_bounds__(256)
void attn_kernel(const float* __restrict__ Q, const float* __restrict__ Kg,
                 const float* __restrict__ Vg, const int* __restrict__ mask,
                 u16* __restrict__ Oh, u16* __restrict__ Ol)
{
    const int head = blockIdx.y;
    const int q0 = blockIdx.x * 64;
    const int tid = threadIdx.x;
    const int tr = tid >> 4;
    const int tc = tid & 15;

    extern __shared__ float sm[];
    float* sQ = sm;
    float* sK = sm + 64 * SSTR;
    float* sV = sm + 2 * 64 * SSTR;
    float* sP = sK;   // alias: K tile is dead after the score phase

#pragma unroll
    for (int l = 0; l < 4; ++l) {
        int idx = tid + l * 256;
        int r = idx >> 4, c4 = idx & 15;
        *(float4*)(sQ + r * SSTR + c4 * 4) =
            *(const float4*)(Q + (size_t)(q0 + r) * DM + head * DH + c4 * 4);
    }

    float mrow[4], lrow[4];
    float2 acc2[4][2];
#pragma unroll
    for (int r = 0; r < 4; ++r) {
        mrow[r] = -3.0e38f;
        lrow[r] = 0.f;
        acc2[r][0] = make_float2(0.f, 0.f);
        acc2[r][1] = make_float2(0.f, 0.f);
    }

    for (int k0 = 0; k0 < SEQ; k0 += 64) {
        int mreg[4][4];
#pragma unroll
        for (int r = 0; r < 4; ++r) {
            const int* mp = mask + (size_t)(q0 + tr * 4 + r) * SEQ + k0;
#pragma unroll
            for (int c = 0; c < 4; ++c)
                mreg[r][c] = __ldg(mp + tc + 16 * c);
        }

#pragma unroll
        for (int l = 0; l < 4; ++l) {
            int idx = tid + l * 256;
            int r = idx >> 4, c4 = idx & 15;
            *(float4*)(sK + r * SSTR + c4 * 4) =
                *(const float4*)(Kg + (size_t)(k0 + r) * DM + head * DH + c4 * 4);
            *(float4*)(sV + r * SSTR + c4 * 4) =
                *(const float4*)(Vg + (size_t)(k0 + r) * DM + head * DH + c4 * 4);
        }
        __syncthreads();

        float2 s2[4][4];
#pragma unroll
        for (int r = 0; r < 4; ++r)
#pragma unroll
            for (int c = 0; c < 4; ++c) s2[r][c] = make_float2(0.f, 0.f);

#pragma unroll
        for (int d = 0; d < DH; d += 4) {
            float4 qv[4], kv[4];
#pragma unroll
            for (int r = 0; r < 4; ++r)
                qv[r] = *(const float4*)(sQ + (tr * 4 + r) * SSTR + d);
#pragma unroll
            for (int c = 0; c < 4; ++c)
                kv[c] = *(const float4*)(sK + (tc + 16 * c) * SSTR + d);
#pragma unroll
            for (int r = 0; r < 4; ++r) {
                float2 q01 = make_float2(qv[r].x, qv[r].y);
                float2 q23 = make_float2(qv[r].z, qv[r].w);
#pragma unroll
                for (int c = 0; c < 4; ++c) {
                    s2[r][c] = ffma2(q01, make_float2(kv[c].x, kv[c].y), s2[r][c]);
                    s2[r][c] = ffma2(q23, make_float2(kv[c].z, kv[c].w), s2[r][c]);
                }
            }
        }

        float s[4][4];
#pragma unroll
        for (int r = 0; r < 4; ++r)
#pragma unroll
            for (int c = 0; c < 4; ++c) {
                s[r][c] = s2[r][c].x + s2[r][c].y;
                if (mreg[r][c] == 0) s[r][c] = -1.0e9f;
            }

        __syncthreads();

#pragma unroll
        for (int r = 0; r < 4; ++r) {
            float tm = fmaxf(fmaxf(s[r][0], s[r][1]), fmaxf(s[r][2], s[r][3]));
#pragma unroll
            for (int off = 8; off >= 1; off >>= 1)
                tm = fmaxf(tm, __shfl_xor_sync(0xffffffffu, tm, off));
            float nm = fmaxf(mrow[r], tm);
            float sc = __expf(mrow[r] - nm);
            mrow[r] = nm;
            float rs = 0.f;
#pragma unroll
            for (int c = 0; c < 4; ++c) {
                float p = __expf(s[r][c] - nm);
                rs += p;
                sP[(tr * 4 + r) * SSTR + tc + 16 * c] = p;
            }
#pragma unroll
            for (int off = 8; off >= 1; off >>= 1)
                rs += __shfl_xor_sync(0xffffffffu, rs, off);
            lrow[r] = lrow[r] * sc + rs;
            acc2[r][0].x *= sc; acc2[r][0].y *= sc;
            acc2[r][1].x *= sc; acc2[r][1].y *= sc;
        }
        __syncthreads();

#pragma unroll 8
        for (int j = 0; j < 64; ++j) {
            float4 vv = *(const float4*)(sV + j * SSTR + tc * 4);
            float2 v0 = make_float2(vv.x, vv.y);
            float2 v1 = make_float2(vv.z, vv.w);
#pragma unroll
            for (int r = 0; r < 4; ++r) {
                float p = sP[(tr * 4 + r) * SSTR + j];
                float2 pp = make_float2(p, p);
                acc2[r][0] = ffma2(pp, v0, acc2[r][0]);
                acc2[r][1] = ffma2(pp, v1, acc2[r][1]);
            }
        }
        __syncthreads();
    }

#pragma unroll
    for (int r = 0; r < 4; ++r) {
        float inv = 1.f / lrow[r];
        float o0 = acc2[r][0].x * inv, o1 = acc2[r][0].y * inv;
        float o2 = acc2[r][1].x * inv, o3 = acc2[r][1].y * inv;
        u16 h0, l0, h1, l1, h2, l2, h3, l3;
        bf16split(o0, h0, l0); bf16split(o1, h1, l1);
        bf16split(o2, h2, l2); bf16split(o3, h3, l3);
        size_t go = (size_t)(q0 + tr * 4 + r) * DM + head * DH + tc * 4;
        uint2 hv, lv;
        hv.x = (unsigned)h0 | ((unsigned)h1 << 16);
        hv.y = (unsigned)h2 | ((unsigned)h3 << 16);
        lv.x = (unsigned)l0 | ((unsigned)l1 << 16);
        lv.y = (unsigned)l2 | ((unsigned)l3 << 16);
        *(uint2*)(Oh + go) = hv;
        *(uint2*)(Ol + go) = lv;
    }
}

// ---------------- residual + LayerNorm (+ optional bf16 split out) -----------
template <bool OUT_BF16>
__global__ __launch_bounds__(256)
void ln_res_kernel(const float* __restrict__ X, const float* __restrict__ R,
                   const float* __restrict__ g, const float* __restrict__ b,
                   float* __restrict__ out, u16* __restrict__ Oh,
                   u16* __restrict__ Ol)
{
    __shared__ float red[8];
    __shared__ float stat[2];
    const int row = blockIdx.x;
    const int tid = threadIdx.x;
    const int col = tid * 2;

    float2 xv = *(const float2*)(X + (size_t)row * DM + col);
    float2 rv = *(const float2*)(R + (size_t)row * DM + col);
    float a0 = xv.x + rv.x;
    float a1 = xv.y + rv.y;

    float s = a0 + a1;
#pragma unroll
    for (int off = 16; off >= 1; off >>= 1)
        s += __shfl_xor_sync(0xffffffffu, s, off);
    if ((tid & 31) == 0) red[tid >> 5] = s;
    __syncthreads();
    if (tid == 0) {
        float t = 0.f;
#pragma unroll
        for (int i = 0; i < 8; ++i) t += red[i];
        stat[0] = t * (1.f / (float)DM);
    }
    __syncthreads();
    const float mean = stat[0];

    float d0 = a0 - mean, d1 = a1 - mean;
    float sq = d0 * d0 + d1 * d1;
#pragma unroll
    for (int off = 16; off >= 1; off >>= 1)
        sq += __shfl_xor_sync(0xffffffffu, sq, off);
    if ((tid & 31) == 0) red[tid >> 5] = sq;
    __syncthreads();
    if (tid == 0) {
        float t = 0.f;
#pragma unroll
        for (int i = 0; i < 8; ++i) t += red[i];
        stat[1] = t * (1.f / (float)DM);
    }
    __syncthreads();
    const float rstd = rsqrtf(stat[1] + 1e-5f);

    float2 gv = *(const float2*)(g + col);
    float2 bv = *(const float2*)(b + col);
    float o0 = d0 * rstd * gv.x + bv.x;
    float o1 = d1 * rstd * gv.y + bv.y;
    *(float2*)(out + (size_t)row * DM + col) = make_float2(o0, o1);
    if (OUT_BF16) {
        u16 h0, l0, h1, l1;
        bf16split(o0, h0, l0);
        bf16split(o1, h1, l1);
        *(unsigned*)(Oh + (size_t)row * DM + col) =
            (unsigned)h0 | ((unsigned)h1 << 16);
        *(unsigned*)(Ol + (size_t)row * DM + col) =
            (unsigned)l0 | ((unsigned)l1 << 16);
    }
}

// ---------------- launch ------------------------------------------------------
extern "C" void kernel_launch(void* const* d_in, const int* in_sizes, int n_in,
                              void* d_out, int out_size)
{
    (void)in_sizes; (void)n_in; (void)out_size;

    const float* x   = (const float*)d_in[0];
    const int*   msk = (const int*)  d_in[1];
    const float* wq  = (const float*)d_in[2];
    const float* bq  = (const float*)d_in[3];
    const float* wk  = (const float*)d_in[4];
    const float* bk  = (const float*)d_in[5];
    const float* wv  = (const float*)d_in[6];
    const float* bv  = (const float*)d_in[7];
    const float* wo  = (const float*)d_in[8];
    const float* bo  = (const float*)d_in[9];
    const float* w1  = (const float*)d_in[10];
    const float* b1  = (const float*)d_in[11];
    const float* w2  = (const float*)d_in[12];
    const float* b2  = (const float*)d_in[13];
    const float* g1  = (const float*)d_in[14];
    const float* be1 = (const float*)d_in[15];
    const float* g2  = (const float*)d_in[16];
    const float* be2 = (const float*)d_in[17];
    float* out = (float*)d_out;

    float *q, *k, *v, *tmp, *y;
    cudaGetSymbolAddress((void**)&q,   g_q);
    cudaGetSymbolAddress((void**)&k,   g_k);
    cudaGetSymbolAddress((void**)&v,   g_v);
    cudaGetSymbolAddress((void**)&tmp, g_tmp);
    cudaGetSymbolAddress((void**)&y,   g_y);

    u16 *xh, *xl, *ah, *al, *yh, *yl, *hh, *hl;
    u16 *wqh, *wql, *wkh, *wkl, *wvh, *wvl, *woh, *wol, *w1h, *w1l, *w2h, *w2l;
    cudaGetSymbolAddress((void**)&xh, g_xh);  cudaGetSymbolAddress((void**)&xl, g_xl);
    cudaGetSymbolAddress((void**)&ah, g_ah);  cudaGetSymbolAddress((void**)&al, g_al);
    cudaGetSymbolAddress((void**)&yh, g_yh);  cudaGetSymbolAddress((void**)&yl, g_yl);
    cudaGetSymbolAddress((void**)&hh, g_hh);  cudaGetSymbolAddress((void**)&hl, g_hl);
    cudaGetSymbolAddress((void**)&wqh, g_wqh); cudaGetSymbolAddress((void**)&wql, g_wql);
    cudaGetSymbolAddress((void**)&wkh, g_wkh); cudaGetSymbolAddress((void**)&wkl, g_wkl);
    cudaGetSymbolAddress((void**)&wvh, g_wvh); cudaGetSymbolAddress((void**)&wvl, g_wvl);
    cudaGetSymbolAddress((void**)&woh, g_woh); cudaGetSymbolAddress((void**)&wol, g_wol);
    cudaGetSymbolAddress((void**)&w1h, g_w1h); cudaGetSymbolAddress((void**)&w1l, g_w1l);
    cudaGetSymbolAddress((void**)&w2h, g_w2h); cudaGetSymbolAddress((void**)&w2l, g_w2l);

    const dim3 blk(256);

    // ---- operand preparation (once per call, O(M*K) not O(M*K*N)) ----
    split_act<<<(SEQ * DM / 4 + 255) / 256, blk>>>(x, xh, xl, SEQ * DM);
    transpose_split<<<dim3(DM / 32, DM / 32), blk>>>(wq, wqh, wql, DM, DM);
    transpose_split<<<dim3(DM / 32, DM / 32), blk>>>(wk, wkh, wkl, DM, DM);
    transpose_split<<<dim3(DM / 32, DM / 32), blk>>>(wv, wvh, wvl, DM, DM);
    transpose_split<<<dim3(DM / 32, DM / 32), blk>>>(wo, woh, wol, DM, DM);
    transpose_split<<<dim3(FF / 32, DM / 32), blk>>>(w1, w1h, w1l, DM, FF);
    transpose_split<<<dim3(DM / 32, FF / 32), blk>>>(w2, w2h, w2l, FF, DM);

    // ---- Q/K/V projections ----
    qkv_mma<<<dim3(DM / 64, SEQ / 128, 3), blk>>>(xh, xl, bq, bk, bv, q, k, v);

    // ---- attention (fp32 flash; writes bf16 hi/lo) ----
    const int asmem = 3 * 64 * SSTR * (int)sizeof(float);
    cudaFuncSetAttribute(attn_kernel, cudaFuncAttributeMaxDynamicSharedMemorySize, asmem);
    attn_kernel<<<dim3(SEQ / 64, NH), blk, asmem>>>(q, k, v, msk, ah, al);

    // ---- output projection + residual + LN1 (LN1 also emits bf16 y) ----
    gemm_mma<false, false><<<dim3(DM / 64, SEQ / 128), blk>>>(
        ah, al, woh, wol, bo, tmp, 0, 0, DM, DM);
    ln_res_kernel<true><<<SEQ, blk>>>(x, tmp, g1, be1, y, yh, yl);

    // ---- FFN (FFN1 emits bf16 h directly) ----
    gemm_mma<true, true><<<dim3(FF / 64, SEQ / 128), blk>>>(
        yh, yl, w1h, w1l, b1, 0, hh, hl, FF, DM);
    gemm_mma<false, false><<<dim3(DM / 64, SEQ / 128), blk>>>(
        hh, hl, w2h, w2l, b2, tmp, 0, 0, DM, FF);
    ln_res_kernel<false><<<SEQ, blk>>>(y, tmp, g2, be2, out, 0, 0);
}

// round 17
// speedup vs baseline: 2.8543x; 1.7692x over previous
#include <cuda_runtime.h>
#include <cuda_bf16.h>
#include <math.h>
#include <float.h>

// Problem constants
#define SEQ 4096
#define DM  512
#define FF  2048
#define NH  8
#define DH  64

typedef unsigned short u16;

// ---------------- scratch (allocation-free: __device__ globals) ----------------
__device__ float g_tmp[SEQ * DM];
__device__ float g_y[SEQ * DM];

// bf16 hi/lo operand buffers
__device__ u16 g_xh[SEQ * DM],  g_xl[SEQ * DM];    // split(x)
__device__ u16 g_qh[SEQ * DM],  g_ql[SEQ * DM];    // Q projection
__device__ u16 g_kh[SEQ * DM],  g_kl[SEQ * DM];    // K projection
__device__ u16 g_vh[SEQ * DM],  g_vl[SEQ * DM];    // V projection
__device__ u16 g_ah[SEQ * DM],  g_al[SEQ * DM];    // attention output
__device__ u16 g_yh[SEQ * DM],  g_yl[SEQ * DM];    // LN1 output
__device__ u16 g_hh[SEQ * FF],  g_hl[SEQ * FF];    // FFN1 ReLU output
// transposed weights [N][K]
__device__ u16 g_wqh[DM * DM], g_wql[DM * DM];
__device__ u16 g_wkh[DM * DM], g_wkl[DM * DM];
__device__ u16 g_wvh[DM * DM], g_wvl[DM * DM];
__device__ u16 g_woh[DM * DM], g_wol[DM * DM];
__device__ u16 g_w1h[FF * DM], g_w1l[FF * DM];
__device__ u16 g_w2h[DM * FF], g_w2l[DM * FF];

// ---------------- helpers -----------------------------------------------------
__device__ __forceinline__ unsigned smem_u32(const void* p)
{
    unsigned a;
    asm("{ .reg .u64 t; cvta.to.shared.u64 t, %1; cvt.u32.u64 %0, t; }"
        : "=r"(a) : "l"(p));
    return a;
}

__device__ __forceinline__ void ldsm4(unsigned* r, unsigned addr)
{
    asm volatile("ldmatrix.sync.aligned.m8n8.x4.shared.b16 {%0,%1,%2,%3}, [%4];"
                 : "=r"(r[0]), "=r"(r[1]), "=r"(r[2]), "=r"(r[3]) : "r"(addr));
}

__device__ __forceinline__ void ldsm4t(unsigned* r, unsigned addr)
{
    asm volatile("ldmatrix.sync.aligned.m8n8.x4.trans.shared.b16 {%0,%1,%2,%3}, [%4];"
                 : "=r"(r[0]), "=r"(r[1]), "=r"(r[2]), "=r"(r[3]) : "r"(addr));
}

__device__ __forceinline__ void mma16816(float* c, const unsigned* a,
                                         const unsigned* b)
{
    asm volatile("mma.sync.aligned.m16n8k16.row.col.f32.bf16.bf16.f32 "
                 "{%0,%1,%2,%3}, {%4,%5,%6,%7}, {%8,%9}, {%0,%1,%2,%3};"
                 : "+f"(c[0]), "+f"(c[1]), "+f"(c[2]), "+f"(c[3])
                 : "r"(a[0]), "r"(a[1]), "r"(a[2]), "r"(a[3]),
                   "r"(b[0]), "r"(b[1]));
}

__device__ __forceinline__ void bf16split(float f, u16& h, u16& l)
{
    __nv_bfloat16 hb = __float2bfloat16(f);
    float rem = f - __bfloat162float(hb);
    __nv_bfloat16 lb = __float2bfloat16(rem);
    h = __bfloat16_as_ushort(hb);
    l = __bfloat16_as_ushort(lb);
}

// pack two fp32 into bf16x2 hi-reg and lo-reg (low 16 bits = first value)
__device__ __forceinline__ void pack2(float a, float b, unsigned& h, unsigned& l)
{
    u16 ha, la, hb, lb;
    bf16split(a, ha, la);
    bf16split(b, hb, lb);
    h = (unsigned)ha | ((unsigned)hb << 16);
    l = (unsigned)la | ((unsigned)lb << 16);
}

// ---------------- conversion kernels ------------------------------------------
__global__ __launch_bounds__(256)
void split_act(const float* __restrict__ X, u16* __restrict__ H,
               u16* __restrict__ L, int n)
{
    int i = (blockIdx.x * 256 + threadIdx.x) * 4;
    if (i >= n) return;
    float4 f = *(const float4*)(X + i);
    u16 h0, l0, h1, l1, h2, l2, h3, l3;
    bf16split(f.x, h0, l0); bf16split(f.y, h1, l1);
    bf16split(f.z, h2, l2); bf16split(f.w, h3, l3);
    uint2 hv, lv;
    hv.x = (unsigned)h0 | ((unsigned)h1 << 16);
    hv.y = (unsigned)h2 | ((unsigned)h3 << 16);
    lv.x = (unsigned)l0 | ((unsigned)l1 << 16);
    lv.y = (unsigned)l2 | ((unsigned)l3 << 16);
    *(uint2*)(H + i) = hv;
    *(uint2*)(L + i) = lv;
}

__global__ __launch_bounds__(256)
void transpose_split(const float* __restrict__ W, u16* __restrict__ Th,
                     u16* __restrict__ Tl, int K, int N)
{
    __shared__ float tile[32][33];
    const int k0 = blockIdx.y * 32, n0 = blockIdx.x * 32;
    const int tx = threadIdx.x & 31, ty = threadIdx.x >> 5;
#pragma unroll
    for (int i = 0; i < 32; i += 8)
        tile[ty + i][tx] = W[(size_t)(k0 + ty + i) * N + n0 + tx];
    __syncthreads();
#pragma unroll
    for (int i = 0; i < 32; i += 8) {
        float f = tile[tx][ty + i];
        u16 h, l;
        bf16split(f, h, l);
        size_t o = (size_t)(n0 + ty + i) * K + k0 + tx;
        Th[o] = h;
        Tl[o] = l;
    }
}

// ---------------- tensor-core GEMM on pre-split bf16 (validated R16) ----------
#define ASTR 40

template <bool RELU, bool OUT_BF16>
__device__ __forceinline__
void gemm_mma_body(const u16* __restrict__ Ah, const u16* __restrict__ Al,
                   const u16* __restrict__ Bh, const u16* __restrict__ Bl,
                   const float* __restrict__ bias,
                   float* __restrict__ C, u16* __restrict__ Ch,
                   u16* __restrict__ Cl, int N, int K, int m0, int n0)
{
    __shared__ __align__(16) u16 sAh[128 * ASTR];
    __shared__ __align__(16) u16 sAl[128 * ASTR];
    __shared__ __align__(16) u16 sBh[64 * ASTR];
    __shared__ __align__(16) u16 sBl[64 * ASTR];

    const int tid  = threadIdx.x;
    const int wid  = tid >> 5;
    const int lane = tid & 31;
    const int wm   = wid >> 1;
    const int wn   = wid & 1;

    float c[2][4][4];
#pragma unroll
    for (int mt = 0; mt < 2; ++mt)
#pragma unroll
        for (int nt = 0; nt < 4; ++nt)
#pragma unroll
            for (int i = 0; i < 4; ++i) c[mt][nt][i] = 0.f;

    const unsigned baseAh = smem_u32(sAh), baseAl = smem_u32(sAl);
    const unsigned baseBh = smem_u32(sBh), baseBl = smem_u32(sBl);

    const int nchunks = K >> 5;
    for (int ch = 0; ch < nchunks; ++ch) {
        const int k0 = ch << 5;

#pragma unroll
        for (int it = 0; it < 2; ++it) {
            int idx = tid + it * 256;
            int row = idx >> 2, seg = idx & 3;
            size_t go = (size_t)(m0 + row) * K + k0 + seg * 8;
            int so = row * ASTR + seg * 8;
            *(uint4*)(sAh + so) = *(const uint4*)(Ah + go);
            *(uint4*)(sAl + so) = *(const uint4*)(Al + go);
        }
        {
            int row = tid >> 2, seg = tid & 3;
            size_t go = (size_t)(n0 + row) * K + k0 + seg * 8;
            int so = row * ASTR + seg * 8;
            *(uint4*)(sBh + so) = *(const uint4*)(Bh + go);
            *(uint4*)(sBl + so) = *(const uint4*)(Bl + go);
        }
        __syncthreads();

#pragma unroll
        for (int ks = 0; ks < 2; ++ks) {
            unsigned ah[2][4], al[2][4];
#pragma unroll
            for (int mt = 0; mt < 2; ++mt) {
                int row = wm * 32 + mt * 16 + (lane & 7) + ((lane >> 3) & 1) * 8;
                int kc  = ks * 16 + (lane >> 4) * 8;
                unsigned off = (unsigned)(row * ASTR + kc) * 2;
                ldsm4(ah[mt], baseAh + off);
                ldsm4(al[mt], baseAl + off);
            }
            unsigned bh[4][2], bl[4][2];
#pragma unroll
            for (int ntp = 0; ntp < 2; ++ntp) {
                int nrow = wn * 32 + ntp * 16 + (lane & 7) + ((lane >> 4) & 1) * 8;
                int kc   = ks * 16 + ((lane >> 3) & 1) * 8;
                unsigned off = (unsigned)(nrow * ASTR + kc) * 2;
                unsigned t[4];
                ldsm4(t, baseBh + off);
                bh[ntp * 2 + 0][0] = t[0]; bh[ntp * 2 + 0][1] = t[1];
                bh[ntp * 2 + 1][0] = t[2]; bh[ntp * 2 + 1][1] = t[3];
                ldsm4(t, baseBl + off);
                bl[ntp * 2 + 0][0] = t[0]; bl[ntp * 2 + 0][1] = t[1];
                bl[ntp * 2 + 1][0] = t[2]; bl[ntp * 2 + 1][1] = t[3];
            }
#pragma unroll
            for (int mt = 0; mt < 2; ++mt)
#pragma unroll
                for (int nt = 0; nt < 4; ++nt) {
                    mma16816(c[mt][nt], ah[mt], bh[nt]);
                    mma16816(c[mt][nt], ah[mt], bl[nt]);
                    mma16816(c[mt][nt], al[mt], bh[nt]);
                }
        }
        __syncthreads();
    }

    const int gid = lane >> 2;
    const int tig = lane & 3;
#pragma unroll
    for (int mt = 0; mt < 2; ++mt) {
        int row = m0 + wm * 32 + mt * 16 + gid;
#pragma unroll
        for (int nt = 0; nt < 4; ++nt) {
            int col = n0 + wn * 32 + nt * 8 + tig * 2;
            float2 bb = *(const float2*)(bias + col);
            float o00 = c[mt][nt][0] + bb.x;
            float o01 = c[mt][nt][1] + bb.y;
            float o10 = c[mt][nt][2] + bb.x;
            float o11 = c[mt][nt][3] + bb.y;
            if (RELU) {
                o00 = fmaxf(o00, 0.f); o01 = fmaxf(o01, 0.f);
                o10 = fmaxf(o10, 0.f); o11 = fmaxf(o11, 0.f);
            }
            if (OUT_BF16) {
                unsigned h, l;
                pack2(o00, o01, h, l);
                *(unsigned*)(Ch + (size_t)row * N + col) = h;
                *(unsigned*)(Cl + (size_t)row * N + col) = l;
                pack2(o10, o11, h, l);
                *(unsigned*)(Ch + (size_t)(row + 8) * N + col) = h;
                *(unsigned*)(Cl + (size_t)(row + 8) * N + col) = l;
            } else {
                *(float2*)(C + (size_t)row * N + col)       = make_float2(o00, o01);
                *(float2*)(C + (size_t)(row + 8) * N + col) = make_float2(o10, o11);
            }
        }
    }
}

template <bool RELU, bool OUT_BF16>
__global__ __launch_bounds__(256)
void gemm_mma(const u16* __restrict__ Ah, const u16* __restrict__ Al,
              const u16* __restrict__ Bh, const u16* __restrict__ Bl,
              const float* __restrict__ bias, float* __restrict__ C,
              u16* __restrict__ Ch, u16* __restrict__ Cl, int N, int K)
{
    gemm_mma_body<RELU, OUT_BF16>(Ah, Al, Bh, Bl, bias, C, Ch, Cl,
                                  N, K, blockIdx.y * 128, blockIdx.x * 64);
}

// Fused Q/K/V projection: outputs bf16 hi/lo directly
__global__ __launch_bounds__(256)
void qkv_mma(const u16* __restrict__ Xh, const u16* __restrict__ Xl,
             const float* __restrict__ Bq, const float* __restrict__ Bk,
             const float* __restrict__ Bv)
{
    const u16* Wh; const u16* Wl; const float* Bb; u16* Ch; u16* Cl;
    if (blockIdx.z == 0)      { Wh = g_wqh; Wl = g_wql; Bb = Bq; Ch = g_qh; Cl = g_ql; }
    else if (blockIdx.z == 1) { Wh = g_wkh; Wl = g_wkl; Bb = Bk; Ch = g_kh; Cl = g_kl; }
    else                      { Wh = g_wvh; Wl = g_wvl; Bb = Bv; Ch = g_vh; Cl = g_vl; }
    gemm_mma_body<false, true>(Xh, Xl, Wh, Wl, Bb, 0, Ch, Cl,
                               DM, DM, blockIdx.y * 128, blockIdx.x * 64);
}

// ---------------- mma.sync flash attention (bf16 hi/lo, fp32 softmax) --------
// CTA: 64 q-rows x 1 head. 128 threads = 4 warps; warp w owns rows w*16..+15.
// KV tiles of 64 tokens. Smem row stride 72 u16 (144B: conflict-free ldmatrix).
#define VSTR 72

__global__ __launch_bounds__(128)
void attn_mma(const u16* __restrict__ Qh, const u16* __restrict__ Ql,
              const u16* __restrict__ Kh, const u16* __restrict__ Kl,
              const u16* __restrict__ Vh, const u16* __restrict__ Vl,
              const int* __restrict__ mask,
              u16* __restrict__ Oh, u16* __restrict__ Ol)
{
    extern __shared__ u16 smu[];
    u16* sQh = smu;                  // 64*72
    u16* sQl = smu + 4608;
    u16* sKh = smu + 9216;
    u16* sKl = smu + 13824;
    u16* sVh = smu + 18432;
    u16* sVl = smu + 23040;          // total 27648 u16 = 55296 B

    const int head = blockIdx.y;
    const int q0   = blockIdx.x * 64;
    const int tid  = threadIdx.x;
    const int w    = tid >> 5;
    const int lane = tid & 31;
    const int gid  = lane >> 2;
    const int tig  = lane & 3;
    const int hoff = head * DH;

    // stage Q tile (64 rows x 64 bf16, hi+lo)
#pragma unroll
    for (int it = 0; it < 4; ++it) {
        int idx = tid + it * 128;
        int row = idx >> 3, seg = idx & 7;
        size_t go = (size_t)(q0 + row) * DM + hoff + seg * 8;
        *(uint4*)(sQh + row * VSTR + seg * 8) = *(const uint4*)(Qh + go);
        *(uint4*)(sQl + row * VSTR + seg * 8) = *(const uint4*)(Ql + go);
    }
    __syncthreads();

    // Q fragments held in registers for the whole kernel (4 kchunks x 4 regs)
    unsigned qfh[4][4], qfl[4][4];
    {
        int row = w * 16 + (lane & 7) + ((lane >> 3) & 1) * 8;
        unsigned bQh = smem_u32(sQh), bQl = smem_u32(sQl);
#pragma unroll
        for (int c = 0; c < 4; ++c) {
            unsigned off = (unsigned)(row * VSTR + c * 16 + (lane >> 4) * 8) * 2;
            ldsm4(qfh[c], bQh + off);
            ldsm4(qfl[c], bQl + off);
        }
    }

    float o[8][4];
#pragma unroll
    for (int nt = 0; nt < 8; ++nt)
#pragma unroll
        for (int i = 0; i < 4; ++i) o[nt][i] = 0.f;
    float m0 = -3.0e38f, m1 = -3.0e38f, l0 = 0.f, l1 = 0.f;

    const unsigned bKh = smem_u32(sKh), bKl = smem_u32(sKl);
    const unsigned bVh = smem_u32(sVh), bVl = smem_u32(sVl);

    for (int k0 = 0; k0 < SEQ; k0 += 64) {
        // mask prefetch (rows gid / gid+8 of this warp's 16 rows)
        int2 mr[8][2];
        {
            const int* mp0 = mask + (size_t)(q0 + w * 16 + gid) * SEQ + k0;
            const int* mp1 = mp0 + 8 * SEQ;
#pragma unroll
            for (int nt = 0; nt < 8; ++nt) {
                mr[nt][0] = *(const int2*)(mp0 + nt * 8 + tig * 2);
                mr[nt][1] = *(const int2*)(mp1 + nt * 8 + tig * 2);
            }
        }

        // stage K/V tiles (hi+lo)
#pragma unroll
        for (int it = 0; it < 4; ++it) {
            int idx = tid + it * 128;
            int row = idx >> 3, seg = idx & 7;
            size_t go = (size_t)(k0 + row) * DM + hoff + seg * 8;
            *(uint4*)(sKh + row * VSTR + seg * 8) = *(const uint4*)(Kh + go);
            *(uint4*)(sKl + row * VSTR + seg * 8) = *(const uint4*)(Kl + go);
            *(uint4*)(sVh + row * VSTR + seg * 8) = *(const uint4*)(Vh + go);
            *(uint4*)(sVl + row * VSTR + seg * 8) = *(const uint4*)(Vl + go);
        }
        __syncthreads();

        // ---- S = Q K^T (3-product hi/lo split) ----
        float s[8][4];
#pragma unroll
        for (int nt = 0; nt < 8; ++nt)
#pragma unroll
            for (int i = 0; i < 4; ++i) s[nt][i] = 0.f;

#pragma unroll
        for (int p = 0; p < 4; ++p) {
            int nrow = p * 16 + (lane & 7) + ((lane >> 4) & 1) * 8;
#pragma unroll
            for (int c = 0; c < 4; ++c) {
                unsigned off = (unsigned)(nrow * VSTR + c * 16 +
                                          ((lane >> 3) & 1) * 8) * 2;
                unsigned th[4], tl[4];
                ldsm4(th, bKh + off);
                ldsm4(tl, bKl + off);
                mma16816(s[2 * p],     qfh[c], th);
                mma16816(s[2 * p],     qfh[c], tl);
                mma16816(s[2 * p],     qfl[c], th);
                mma16816(s[2 * p + 1], qfh[c], th + 2);
                mma16816(s[2 * p + 1], qfh[c], tl + 2);
                mma16816(s[2 * p + 1], qfl[c], th + 2);
            }
        }

        // ---- mask ----
#pragma unroll
        for (int nt = 0; nt < 8; ++nt) {
            if (mr[nt][0].x == 0) s[nt][0] = -1.0e9f;
            if (mr[nt][0].y == 0) s[nt][1] = -1.0e9f;
            if (mr[nt][1].x == 0) s[nt][2] = -1.0e9f;
            if (mr[nt][1].y == 0) s[nt][3] = -1.0e9f;
        }

        // ---- online softmax (quad shfl: each row lives in one 4-lane group) --
        float tm0 = -3.0e38f, tm1 = -3.0e38f;
#pragma unroll
        for (int nt = 0; nt < 8; ++nt) {
            tm0 = fmaxf(tm0, fmaxf(s[nt][0], s[nt][1]));
            tm1 = fmaxf(tm1, fmaxf(s[nt][2], s[nt][3]));
        }
        tm0 = fmaxf(tm0, __shfl_xor_sync(0xffffffffu, tm0, 1));
        tm0 = fmaxf(tm0, __shfl_xor_sync(0xffffffffu, tm0, 2));
        tm1 = fmaxf(tm1, __shfl_xor_sync(0xffffffffu, tm1, 1));
        tm1 = fmaxf(tm1, __shfl_xor_sync(0xffffffffu, tm1, 2));

        float nm0 = fmaxf(m0, tm0), nm1 = fmaxf(m1, tm1);
        float sc0 = __expf(m0 - nm0), sc1 = __expf(m1 - nm1);
        m0 = nm0; m1 = nm1;

        float rs0 = 0.f, rs1 = 0.f;
#pragma unroll
        for (int nt = 0; nt < 8; ++nt) {
            s[nt][0] = __expf(s[nt][0] - nm0);
            s[nt][1] = __expf(s[nt][1] - nm0);
            s[nt][2] = __expf(s[nt][2] - nm1);
            s[nt][3] = __expf(s[nt][3] - nm1);
            rs0 += s[nt][0] + s[nt][1];
            rs1 += s[nt][2] + s[nt][3];
        }
        rs0 += __shfl_xor_sync(0xffffffffu, rs0, 1);
        rs0 += __shfl_xor_sync(0xffffffffu, rs0, 2);
        rs1 += __shfl_xor_sync(0xffffffffu, rs1, 1);
        rs1 += __shfl_xor_sync(0xffffffffu, rs1, 2);
        l0 = l0 * sc0 + rs0;
        l1 = l1 * sc1 + rs1;

#pragma unroll
        for (int nt = 0; nt < 8; ++nt) {
            o[nt][0] *= sc0; o[nt][1] *= sc0;
            o[nt][2] *= sc1; o[nt][3] *= sc1;
        }

        // ---- O += P V : P from S-fragments (C->A layout identity), V trans --
#pragma unroll
        for (int c = 0; c < 4; ++c) {
            unsigned ph[4], pl[4];
            pack2(s[2 * c][0],     s[2 * c][1],     ph[0], pl[0]);
            pack2(s[2 * c][2],     s[2 * c][3],     ph[1], pl[1]);
            pack2(s[2 * c + 1][0], s[2 * c + 1][1], ph[2], pl[2]);
            pack2(s[2 * c + 1][2], s[2 * c + 1][3], ph[3], pl[3]);

            int vrow = c * 16 + (lane & 7) + ((lane >> 3) & 1) * 8;
#pragma unroll
            for (int np = 0; np < 4; ++np) {
                unsigned off = (unsigned)(vrow * VSTR + np * 16 +
                                          ((lane >> 4) & 1) * 8) * 2;
                unsigned th[4], tl[4];
                ldsm4t(th, bVh + off);
                ldsm4t(tl, bVl + off);
                mma16816(o[2 * np],     ph, th);
                mma16816(o[2 * np],     ph, tl);
                mma16816(o[2 * np],     pl, th);
                mma16816(o[2 * np + 1], ph, th + 2);
                mma16816(o[2 * np + 1], ph, tl + 2);
                mma16816(o[2 * np + 1], pl, th + 2);
            }
        }
        __syncthreads();
    }

    // ---- epilogue: normalize + bf16 hi/lo store ----
    float inv0 = 1.f / l0, inv1 = 1.f / l1;
    int row0 = q0 + w * 16 + gid;
#pragma unroll
    for (int nt = 0; nt < 8; ++nt) {
        int col = hoff + nt * 8 + tig * 2;
        unsigned h, l;
        pack2(o[nt][0] * inv0, o[nt][1] * inv0, h, l);
        *(unsigned*)(Oh + (size_t)row0 * DM + col) = h;
        *(unsigned*)(Ol + (size_t)row0 * DM + col) = l;
        pack2(o[nt][2] * inv1, o[nt][3] * inv1, h, l);
        *(unsigned*)(Oh + (size_t)(row0 + 8) * DM + col) = h;
        *(unsigned*)(Ol + (size_t)(row0 + 8) * DM + col) = l;
    }
}

// ---------------- residual + LayerNorm (+ optional bf16 split out) -----------
template <bool OUT_BF16>
__global__ __launch_bounds__(256)
void ln_res_kernel(const float* __restrict__ X, const float* __restrict__ R,
                   const float* __restrict__ g, const float* __restrict__ b,
                   float* __restrict__ out, u16* __restrict__ Oh,
                   u16* __restrict__ Ol)
{
    __shared__ float red[8];
    __shared__ float stat[2];
    const int row = blockIdx.x;
    const int tid = threadIdx.x;
    const int col = tid * 2;

    float2 xv = *(const float2*)(X + (size_t)row * DM + col);
    float2 rv = *(const float2*)(R + (size_t)row * DM + col);
    float a0 = xv.x + rv.x;
    float a1 = xv.y + rv.y;

    float s = a0 + a1;
#pragma unroll
    for (int off = 16; off >= 1; off >>= 1)
        s += __shfl_xor_sync(0xffffffffu, s, off);
    if ((tid & 31) == 0) red[tid >> 5] = s;
    __syncthreads();
    if (tid == 0) {
        float t = 0.f;
#pragma unroll
        for (int i = 0; i < 8; ++i) t += red[i];
        stat[0] = t * (1.f / (float)DM);
    }
    __syncthreads();
    const float mean = stat[0];

    float d0 = a0 - mean, d1 = a1 - mean;
    float sq = d0 * d0 + d1 * d1;
#pragma unroll
    for (int off = 16; off >= 1; off >>= 1)
        sq += __shfl_xor_sync(0xffffffffu, sq, off);
    if ((tid & 31) == 0) red[tid >> 5] = sq;
    __syncthreads();
    if (tid == 0) {
        float t = 0.f;
#pragma unroll
        for (int i = 0; i < 8; ++i) t += red[i];
        stat[1] = t * (1.f / (float)DM);
    }
    __syncthreads();
    const float rstd = rsqrtf(stat[1] + 1e-5f);

    float2 gv = *(const float2*)(g + col);
    float2 bv = *(const float2*)(b + col);
    float o0 = d0 * rstd * gv.x + bv.x;
    float o1 = d1 * rstd * gv.y + bv.y;
    *(float2*)(out + (size_t)row * DM + col) = make_float2(o0, o1);
    if (OUT_BF16) {
        unsigned h, l;
        pack2(o0, o1, h, l);
        *(unsigned*)(Oh + (size_t)row * DM + col) = h;
        *(unsigned*)(Ol + (size_t)row * DM + col) = l;
    }
}

// ---------------- launch ------------------------------------------------------
extern "C" void kernel_launch(void* const* d_in, const int* in_sizes, int n_in,
                              void* d_out, int out_size)
{
    (void)in_sizes; (void)n_in; (void)out_size;

    const float* x   = (const float*)d_in[0];
    const int*   msk = (const int*)  d_in[1];
    const float* wq  = (const float*)d_in[2];
    const float* bq  = (const float*)d_in[3];
    const float* wk  = (const float*)d_in[4];
    const float* bk  = (const float*)d_in[5];
    const float* wv  = (const float*)d_in[6];
    const float* bv  = (const float*)d_in[7];
    const float* wo  = (const float*)d_in[8];
    const float* bo  = (const float*)d_in[9];
    const float* w1  = (const float*)d_in[10];
    const float* b1  = (const float*)d_in[11];
    const float* w2  = (const float*)d_in[12];
    const float* b2  = (const float*)d_in[13];
    const float* g1  = (const float*)d_in[14];
    const float* be1 = (const float*)d_in[15];
    const float* g2  = (const float*)d_in[16];
    const float* be2 = (const float*)d_in[17];
    float* out = (float*)d_out;

    float *tmp, *y;
    cudaGetSymbolAddress((void**)&tmp, g_tmp);
    cudaGetSymbolAddress((void**)&y,   g_y);

    u16 *xh, *xl, *qh, *ql, *kh, *kl, *vh, *vl, *ah, *al, *yh, *yl, *hh, *hl;
    u16 *wqh, *wql, *wkh, *wkl, *wvh, *wvl, *woh, *wol, *w1h, *w1l, *w2h, *w2l;
    cudaGetSymbolAddress((void**)&xh, g_xh);  cudaGetSymbolAddress((void**)&xl, g_xl);
    cudaGetSymbolAddress((void**)&qh, g_qh);  cudaGetSymbolAddress((void**)&ql, g_ql);
    cudaGetSymbolAddress((void**)&kh, g_kh);  cudaGetSymbolAddress((void**)&kl, g_kl);
    cudaGetSymbolAddress((void**)&vh, g_vh);  cudaGetSymbolAddress((void**)&vl, g_vl);
    cudaGetSymbolAddress((void**)&ah, g_ah);  cudaGetSymbolAddress((void**)&al, g_al);
    cudaGetSymbolAddress((void**)&yh, g_yh);  cudaGetSymbolAddress((void**)&yl, g_yl);
    cudaGetSymbolAddress((void**)&hh, g_hh);  cudaGetSymbolAddress((void**)&hl, g_hl);
    cudaGetSymbolAddress((void**)&wqh, g_wqh); cudaGetSymbolAddress((void**)&wql, g_wql);
    cudaGetSymbolAddress((void**)&wkh, g_wkh); cudaGetSymbolAddress((void**)&wkl, g_wkl);
    cudaGetSymbolAddress((void**)&wvh, g_wvh); cudaGetSymbolAddress((void**)&wvl, g_wvl);
    cudaGetSymbolAddress((void**)&woh, g_woh); cudaGetSymbolAddress((void**)&wol, g_wol);
    cudaGetSymbolAddress((void**)&w1h, g_w1h); cudaGetSymbolAddress((void**)&w1l, g_w1l);
    cudaGetSymbolAddress((void**)&w2h, g_w2h); cudaGetSymbolAddress((void**)&w2l, g_w2l);

    const dim3 blk(256);

    // ---- operand preparation ----
    split_act<<<(SEQ * DM / 4 + 255) / 256, blk>>>(x, xh, xl, SEQ * DM);
    transpose_split<<<dim3(DM / 32, DM / 32), blk>>>(wq, wqh, wql, DM, DM);
    transpose_split<<<dim3(DM / 32, DM / 32), blk>>>(wk, wkh, wkl, DM, DM);
    transpose_split<<<dim3(DM / 32, DM / 32), blk>>>(wv, wvh, wvl, DM, DM);
    transpose_split<<<dim3(DM / 32, DM / 32), blk>>>(wo, woh, wol, DM, DM);
    transpose_split<<<dim3(FF / 32, DM / 32), blk>>>(w1, w1h, w1l, DM, FF);
    transpose_split<<<dim3(DM / 32, FF / 32), blk>>>(w2, w2h, w2l, FF, DM);

    // ---- Q/K/V projections (emit bf16 hi/lo) ----
    qkv_mma<<<dim3(DM / 64, SEQ / 128, 3), blk>>>(xh, xl, bq, bk, bv);

    // ---- attention (mma.sync bf16 hi/lo flash) ----
    const int asmem = 27648 * (int)sizeof(u16);   // 55296 B
    cudaFuncSetAttribute(attn_mma, cudaFuncAttributeMaxDynamicSharedMemorySize, asmem);
    attn_mma<<<dim3(SEQ / 64, NH), dim3(128), asmem>>>(
        qh, ql, kh, kl, vh, vl, msk, ah, al);

    // ---- output projection + residual + LN1 (LN1 emits bf16 y) ----
    gemm_mma<false, false><<<dim3(DM / 64, SEQ / 128), blk>>>(
        ah, al, woh, wol, bo, tmp, 0, 0, DM, DM);
    ln_res_kernel<true><<<SEQ, blk>>>(x, tmp, g1, be1, y, yh, yl);

    // ---- FFN ----
    gemm_mma<true, true><<<dim3(FF / 64, SEQ / 128), blk>>>(
        yh, yl, w1h, w1l, b1, 0, hh, hl, FF, DM);
    gemm_mma<false, false><<<dim3(DM / 64, SEQ / 128), blk>>>(
        hh, hl, w2h, w2l, b2, tmp, 0, 0, DM, FF);
    ln_res_kernel<false><<<SEQ, blk>>>(y, tmp, g2, be2, out, 0, 0);
}